// round 1
// baseline (speedup 1.0000x reference)
#include <cuda_runtime.h>
#include <cuda_bf16.h>

// GCN encoder: 2x GCNConv(relu) + fused mu/logvar GCNConv heads.
// Strategy:
//   deg/dis -> CSR build (histogram + 1-block scan + cursor fill) ->
//   per layer: [GEMM: g = (X@W) * dis] -> [AGG (pull, warp/node): out = act(dis*(g[i]+sum g[src]) + b)]
// No fp32 atomics anywhere; CSR rebuilt every launch (deterministic work).

#define NMAX 100000
#define EMAX 1600000

__device__ __align__(16) float g_buf[(size_t)NMAX * 64];
__device__ __align__(16) float h_buf[(size_t)NMAX * 64];
__device__ float dis_buf[NMAX];
__device__ int   deg_buf[NMAX];
__device__ int   offs_buf[NMAX + 1];
__device__ int   cursor_buf[NMAX];
__device__ int   csr_buf[EMAX];

// ---------------------------------------------------------------------------
__global__ void zero_deg_kernel(int N) {
    int i = blockIdx.x * blockDim.x + threadIdx.x;
    if (i < N) deg_buf[i] = 0;
}

__global__ void count_deg_kernel(const int* __restrict__ ei, int E) {
    int e = blockIdx.x * blockDim.x + threadIdx.x;
    if (e < E) atomicAdd(&deg_buf[ei[E + e]], 1);
}

__global__ void compute_dis_kernel(int N) {
    int i = blockIdx.x * blockDim.x + threadIdx.x;
    if (i < N) dis_buf[i] = rsqrtf((float)deg_buf[i] + 1.0f);
}

// Single-block Hillis-Steele chunked exclusive scan of deg -> offs (+cursor copy).
__global__ void scan_deg_kernel(int N, int E) {
    __shared__ int sh[1024];
    __shared__ int carry;
    int tid = threadIdx.x;
    if (tid == 0) carry = 0;
    __syncthreads();
    for (int base = 0; base < N; base += 1024) {
        int idx = base + tid;
        int v = (idx < N) ? deg_buf[idx] : 0;
        sh[tid] = v;
        __syncthreads();
        #pragma unroll
        for (int off = 1; off < 1024; off <<= 1) {
            int t = (tid >= off) ? sh[tid - off] : 0;
            __syncthreads();
            sh[tid] += t;
            __syncthreads();
        }
        int excl = sh[tid] - v + carry;
        if (idx < N) {
            offs_buf[idx]   = excl;
            cursor_buf[idx] = excl;
        }
        __syncthreads();
        if (tid == 0) carry += sh[1023];
        __syncthreads();
    }
    if (tid == 0) offs_buf[N] = carry;
}

__global__ void fill_csr_kernel(const int* __restrict__ ei, int E) {
    int e = blockIdx.x * blockDim.x + threadIdx.x;
    if (e < E) {
        int dst = ei[E + e];
        int p = atomicAdd(&cursor_buf[dst], 1);
        csr_buf[p] = ei[e];  // src
    }
}

// ---------------------------------------------------------------------------
// GEMM + row-scale: out[i, 0:64] = (X[i, 0:K] @ W) * dis[i]
// One warp per row. W staged in shared. Lane computes cols (lane, lane+32).
// COMBINED: W is [Wa | Wb], each K x 32 (mu/logvar heads fused).
template <int K, bool COMBINED>
__global__ void __launch_bounds__(1024, 2)
gemm_scale_kernel(const float* __restrict__ X,
                  const float* __restrict__ Wa,
                  const float* __restrict__ Wb,
                  float* __restrict__ out, int N)
{
    __shared__ float Ws[K * 64];
    int tid = threadIdx.x;
    for (int i = tid; i < K * 64; i += blockDim.x) {
        int k = i >> 6, j = i & 63;
        float v;
        if (COMBINED) v = (j < 32) ? Wa[k * 32 + j] : Wb[k * 32 + (j - 32)];
        else          v = Wa[i];
        Ws[i] = v;
    }
    __syncthreads();

    int warp = (int)((blockIdx.x * (unsigned)blockDim.x + tid) >> 5);
    int lane = tid & 31;
    if (warp >= N) return;
    int row = warp;

    const float* xr = X + (size_t)row * K;
    float xv[K / 32];
    #pragma unroll
    for (int j = 0; j < K / 32; j++) xv[j] = xr[j * 32 + lane];

    float a0 = 0.f, a1 = 0.f;
    #pragma unroll
    for (int j = 0; j < K / 32; j++) {
        #pragma unroll
        for (int t = 0; t < 32; t++) {
            float xk = __shfl_sync(0xffffffffu, xv[j], t);
            int k = j * 32 + t;
            a0 = fmaf(xk, Ws[k * 64 + lane], a0);
            a1 = fmaf(xk, Ws[k * 64 + 32 + lane], a1);
        }
    }
    float d = dis_buf[row];
    out[(size_t)row * 64 + lane]      = a0 * d;
    out[(size_t)row * 64 + 32 + lane] = a1 * d;
}

// ---------------------------------------------------------------------------
// Pull aggregation: one warp per dst node, lane holds cols {2l, 2l+1} (float2).
//   acc = g[row] + sum_{e in row} g[csr[e]]
//   r   = dis[row]*acc + bias ; optional relu ; optional mu/logvar split write.
template <bool RELU, bool SPLIT>
__global__ void agg_kernel(const float* __restrict__ g,
                           const float* __restrict__ ba,
                           const float* __restrict__ bb,
                           float* __restrict__ out, int N)
{
    int warp = (int)((blockIdx.x * (unsigned)blockDim.x + threadIdx.x) >> 5);
    int lane = threadIdx.x & 31;
    if (warp >= N) return;
    int row = warp;

    const float2* gp = (const float2*)g;
    float2 acc = gp[(size_t)row * 32 + lane];   // self-loop term (g[row])

    int beg = offs_buf[row];
    int end = offs_buf[row + 1];
    int e = beg;
    // Software pipeline the index load to break the idx->gather dependency chain.
    int s_next = (e < end) ? csr_buf[e] : 0;
    for (; e < end; e++) {
        int s = s_next;
        if (e + 1 < end) s_next = csr_buf[e + 1];
        float2 v = gp[(size_t)s * 32 + lane];
        acc.x += v.x;
        acc.y += v.y;
    }

    float d = dis_buf[row];
    int c0 = 2 * lane;
    float bb0, bb1;
    if (SPLIT) {
        bb0 = (c0 < 32)     ? ba[c0]     : bb[c0 - 32];
        bb1 = (c0 + 1 < 32) ? ba[c0 + 1] : bb[c0 + 1 - 32];
    } else {
        bb0 = ba[c0];
        bb1 = ba[c0 + 1];
    }
    float r0 = fmaf(d, acc.x, bb0);
    float r1 = fmaf(d, acc.y, bb1);
    if (RELU) { r0 = fmaxf(r0, 0.f); r1 = fmaxf(r1, 0.f); }

    if (SPLIT) {
        if (lane < 16) {
            ((float2*)out)[(size_t)row * 16 + lane] = make_float2(r0, r1);               // mu
        } else {
            ((float2*)(out + (size_t)N * 32))[(size_t)row * 16 + (lane - 16)] = make_float2(r0, r1); // logvar
        }
    } else {
        ((float2*)out)[(size_t)row * 32 + lane] = make_float2(r0, r1);
    }
}

// ---------------------------------------------------------------------------
extern "C" void kernel_launch(void* const* d_in, const int* in_sizes, int n_in,
                              void* d_out, int out_size)
{
    const float* x   = (const float*)d_in[0];
    const int*   ei  = (const int*)  d_in[1];
    const float* W1  = (const float*)d_in[2];
    const float* b1  = (const float*)d_in[3];
    const float* W2  = (const float*)d_in[4];
    const float* b2  = (const float*)d_in[5];
    const float* Wmu = (const float*)d_in[6];
    const float* bmu = (const float*)d_in[7];
    const float* Wlv = (const float*)d_in[8];
    const float* blv = (const float*)d_in[9];
    float* out = (float*)d_out;

    int N = in_sizes[0] / 128;
    int E = in_sizes[1] / 2;

    float* g = nullptr;
    float* h = nullptr;
    cudaGetSymbolAddress((void**)&g, g_buf);
    cudaGetSymbolAddress((void**)&h, h_buf);

    // ---- degree / normalization / CSR build ----
    zero_deg_kernel<<<(N + 255) / 256, 256>>>(N);
    count_deg_kernel<<<(E + 255) / 256, 256>>>(ei, E);
    compute_dis_kernel<<<(N + 255) / 256, 256>>>(N);
    scan_deg_kernel<<<1, 1024>>>(N, E);
    fill_csr_kernel<<<(E + 255) / 256, 256>>>(ei, E);

    int gemm_grid = (N + 31) / 32;      // 1024 threads = 32 warps = 32 rows / block
    int agg_grid  = (N + 7) / 8;        // 256 threads = 8 warps = 8 nodes / block

    // ---- layer 1: x(128) -> h(64), relu ----
    gemm_scale_kernel<128, false><<<gemm_grid, 1024>>>(x, W1, nullptr, g, N);
    agg_kernel<true, false><<<agg_grid, 256>>>(g, b1, nullptr, h, N);

    // ---- layer 2: h(64) -> h(64), relu ----
    gemm_scale_kernel<64, false><<<gemm_grid, 1024>>>(h, W2, nullptr, g, N);
    agg_kernel<true, false><<<agg_grid, 256>>>(g, b2, nullptr, h, N);

    // ---- heads: h(64) -> [mu(32) | logvar(32)] ----
    gemm_scale_kernel<64, true><<<gemm_grid, 1024>>>(h, Wmu, Wlv, g, N);
    agg_kernel<false, true><<<agg_grid, 256>>>(g, bmu, blv, out, N);
}

// round 2
// speedup vs baseline: 1.2802x; 1.2802x over previous
#include <cuda_runtime.h>
#include <cuda_bf16.h>

// GCN encoder: 2x GCNConv(relu) + fused mu/logvar GCNConv heads.
//   deg/dis -> CSR build (histogram + MULTI-BLOCK scan + cursor fill) ->
//   per layer: [GEMM: g = (X@W) * dis] -> [AGG (pull, warp/node): out = act(dis*(g[i]+sum g[src]) + b)]
// No fp32 atomics anywhere; CSR rebuilt every launch (deterministic work).

#define NMAX 100000
#define EMAX 1600000
#define SCAN_B 1024
#define SCAN_NB ((NMAX + SCAN_B - 1) / SCAN_B)   // 98

__device__ __align__(16) float g_buf[(size_t)NMAX * 64];
__device__ __align__(16) float h_buf[(size_t)NMAX * 64];
__device__ float dis_buf[NMAX];
__device__ int   deg_buf[NMAX];
__device__ int   offs_buf[NMAX + 1];
__device__ int   cursor_buf[NMAX];
__device__ int   csr_buf[EMAX];
__device__ int   block_sums[128];

// ---------------------------------------------------------------------------
__global__ void zero_deg_kernel(int N) {
    int i = blockIdx.x * blockDim.x + threadIdx.x;
    if (i < N) deg_buf[i] = 0;
}

__global__ void count_deg_kernel(const int* __restrict__ ei, int E) {
    int e = blockIdx.x * blockDim.x + threadIdx.x;
    if (e < E) atomicAdd(&deg_buf[ei[E + e]], 1);
}

// ---- multi-block exclusive scan of deg_buf -> offs_buf ----
// Phase 1: per-block reductions of 1024 elements.
__global__ void reduce_deg_kernel(int N) {
    int idx = blockIdx.x * SCAN_B + threadIdx.x;
    int v = (idx < N) ? deg_buf[idx] : 0;
    #pragma unroll
    for (int o = 16; o; o >>= 1) v += __shfl_down_sync(0xffffffffu, v, o);
    __shared__ int ws[32];
    int lane = threadIdx.x & 31, w = threadIdx.x >> 5;
    if (lane == 0) ws[w] = v;
    __syncthreads();
    if (w == 0) {
        int s = ws[lane];
        #pragma unroll
        for (int o = 16; o; o >>= 1) s += __shfl_down_sync(0xffffffffu, s, o);
        if (lane == 0) block_sums[blockIdx.x] = s;
    }
}

// Phase 2: scan the (<=128) block sums in one small block.
__global__ void scan_sums_kernel(int nb, int N) {
    int tid = threadIdx.x;
    __shared__ int sh[128];
    int v = (tid < nb) ? block_sums[tid] : 0;
    sh[tid] = v;
    __syncthreads();
    #pragma unroll
    for (int o = 1; o < 128; o <<= 1) {
        int t = (tid >= o) ? sh[tid - o] : 0;
        __syncthreads();
        sh[tid] += t;
        __syncthreads();
    }
    if (tid < nb) block_sums[tid] = sh[tid] - v;   // exclusive
    if (tid == 0) offs_buf[N] = sh[127];           // total = E
}

// Phase 3: per-block scan + add block offset; also fuse dis = rsqrt(deg+1).
__global__ void scan_deg_kernel(int N) {
    int idx = blockIdx.x * SCAN_B + threadIdx.x;
    int v = (idx < N) ? deg_buf[idx] : 0;
    int lane = threadIdx.x & 31, w = threadIdx.x >> 5;
    int s = v;
    #pragma unroll
    for (int o = 1; o < 32; o <<= 1) {
        int t = __shfl_up_sync(0xffffffffu, s, o);
        if (lane >= o) s += t;
    }
    __shared__ int ws[32];
    if (lane == 31) ws[w] = s;
    __syncthreads();
    if (w == 0) {
        int t = ws[lane];
        #pragma unroll
        for (int o = 1; o < 32; o <<= 1) {
            int u = __shfl_up_sync(0xffffffffu, t, o);
            if (lane >= o) t += u;
        }
        ws[lane] = t;
    }
    __syncthreads();
    int excl = s - v + (w > 0 ? ws[w - 1] : 0) + block_sums[blockIdx.x];
    if (idx < N) {
        offs_buf[idx]   = excl;
        cursor_buf[idx] = excl;
        dis_buf[idx]    = rsqrtf((float)v + 1.0f);
    }
}

__global__ void fill_csr_kernel(const int* __restrict__ ei, int E) {
    int e = blockIdx.x * blockDim.x + threadIdx.x;
    if (e < E) {
        int dst = ei[E + e];
        int p = atomicAdd(&cursor_buf[dst], 1);
        csr_buf[p] = ei[e];  // src
    }
}

// ---------------------------------------------------------------------------
// GEMM + row-scale: out[i, 0:64] = (X[i, 0:K] @ W) * dis[i]
// One warp per row. W staged in shared. Lane computes cols (lane, lane+32).
// COMBINED: W is [Wa | Wb], each K x 32 (mu/logvar heads fused).
template <int K, bool COMBINED>
__global__ void __launch_bounds__(1024, 2)
gemm_scale_kernel(const float* __restrict__ X,
                  const float* __restrict__ Wa,
                  const float* __restrict__ Wb,
                  float* __restrict__ out, int N)
{
    __shared__ float Ws[K * 64];
    int tid = threadIdx.x;
    for (int i = tid; i < K * 64; i += blockDim.x) {
        int k = i >> 6, j = i & 63;
        float v;
        if (COMBINED) v = (j < 32) ? Wa[k * 32 + j] : Wb[k * 32 + (j - 32)];
        else          v = Wa[i];
        Ws[i] = v;
    }
    __syncthreads();

    int warp = (int)((blockIdx.x * (unsigned)blockDim.x + tid) >> 5);
    int lane = tid & 31;
    if (warp >= N) return;
    int row = warp;

    const float* xr = X + (size_t)row * K;
    float xv[K / 32];
    #pragma unroll
    for (int j = 0; j < K / 32; j++) xv[j] = xr[j * 32 + lane];

    float a0 = 0.f, a1 = 0.f;
    #pragma unroll
    for (int j = 0; j < K / 32; j++) {
        #pragma unroll
        for (int t = 0; t < 32; t++) {
            float xk = __shfl_sync(0xffffffffu, xv[j], t);
            int k = j * 32 + t;
            a0 = fmaf(xk, Ws[k * 64 + lane], a0);
            a1 = fmaf(xk, Ws[k * 64 + 32 + lane], a1);
        }
    }
    float d = dis_buf[row];
    out[(size_t)row * 64 + lane]      = a0 * d;
    out[(size_t)row * 64 + 32 + lane] = a1 * d;
}

// ---------------------------------------------------------------------------
// Pull aggregation: one warp per dst node, lane holds cols {2l, 2l+1} (float2).
//   acc = g[row] + sum_{e in row} g[csr[e]]
//   r   = dis[row]*acc + bias ; optional relu ; optional mu/logvar split write.
template <bool RELU, bool SPLIT>
__global__ void agg_kernel(const float* __restrict__ g,
                           const float* __restrict__ ba,
                           const float* __restrict__ bb,
                           float* __restrict__ out, int N)
{
    int warp = (int)((blockIdx.x * (unsigned)blockDim.x + threadIdx.x) >> 5);
    int lane = threadIdx.x & 31;
    if (warp >= N) return;
    int row = warp;

    const float2* gp = (const float2*)g;
    float2 acc = gp[(size_t)row * 32 + lane];   // self-loop term (g[row])

    int beg = offs_buf[row];
    int end = offs_buf[row + 1];
    int e = beg;
    // Software pipeline the index load to break the idx->gather dependency chain.
    int s_next = (e < end) ? csr_buf[e] : 0;
    for (; e < end; e++) {
        int s = s_next;
        if (e + 1 < end) s_next = csr_buf[e + 1];
        float2 v = gp[(size_t)s * 32 + lane];
        acc.x += v.x;
        acc.y += v.y;
    }

    float d = dis_buf[row];
    int c0 = 2 * lane;
    float bb0, bb1;
    if (SPLIT) {
        bb0 = (c0 < 32)     ? ba[c0]     : bb[c0 - 32];
        bb1 = (c0 + 1 < 32) ? ba[c0 + 1] : bb[c0 + 1 - 32];
    } else {
        bb0 = ba[c0];
        bb1 = ba[c0 + 1];
    }
    float r0 = fmaf(d, acc.x, bb0);
    float r1 = fmaf(d, acc.y, bb1);
    if (RELU) { r0 = fmaxf(r0, 0.f); r1 = fmaxf(r1, 0.f); }

    if (SPLIT) {
        if (lane < 16) {
            ((float2*)out)[(size_t)row * 16 + lane] = make_float2(r0, r1);               // mu
        } else {
            ((float2*)(out + (size_t)N * 32))[(size_t)row * 16 + (lane - 16)] = make_float2(r0, r1); // logvar
        }
    } else {
        ((float2*)out)[(size_t)row * 32 + lane] = make_float2(r0, r1);
    }
}

// ---------------------------------------------------------------------------
extern "C" void kernel_launch(void* const* d_in, const int* in_sizes, int n_in,
                              void* d_out, int out_size)
{
    const float* x   = (const float*)d_in[0];
    const int*   ei  = (const int*)  d_in[1];
    const float* W1  = (const float*)d_in[2];
    const float* b1  = (const float*)d_in[3];
    const float* W2  = (const float*)d_in[4];
    const float* b2  = (const float*)d_in[5];
    const float* Wmu = (const float*)d_in[6];
    const float* bmu = (const float*)d_in[7];
    const float* Wlv = (const float*)d_in[8];
    const float* blv = (const float*)d_in[9];
    float* out = (float*)d_out;

    int N = in_sizes[0] / 128;
    int E = in_sizes[1] / 2;
    int nb = (N + SCAN_B - 1) / SCAN_B;

    float* g = nullptr;
    float* h = nullptr;
    cudaGetSymbolAddress((void**)&g, g_buf);
    cudaGetSymbolAddress((void**)&h, h_buf);

    // ---- degree / normalization / CSR build ----
    zero_deg_kernel<<<(N + 255) / 256, 256>>>(N);
    count_deg_kernel<<<(E + 255) / 256, 256>>>(ei, E);
    reduce_deg_kernel<<<nb, SCAN_B>>>(N);
    scan_sums_kernel<<<1, 128>>>(nb, N);
    scan_deg_kernel<<<nb, SCAN_B>>>(N);
    fill_csr_kernel<<<(E + 255) / 256, 256>>>(ei, E);

    int gemm_grid = (N + 31) / 32;      // 1024 threads = 32 warps = 32 rows / block
    int agg_grid  = (N + 7) / 8;        // 256 threads = 8 warps = 8 nodes / block

    // ---- layer 1: x(128) -> h(64), relu ----
    gemm_scale_kernel<128, false><<<gemm_grid, 1024>>>(x, W1, nullptr, g, N);
    agg_kernel<true, false><<<agg_grid, 256>>>(g, b1, nullptr, h, N);

    // ---- layer 2: h(64) -> h(64), relu ----
    gemm_scale_kernel<64, false><<<gemm_grid, 1024>>>(h, W2, nullptr, g, N);
    agg_kernel<true, false><<<agg_grid, 256>>>(g, b2, nullptr, h, N);

    // ---- heads: h(64) -> [mu(32) | logvar(32)] ----
    gemm_scale_kernel<64, true><<<gemm_grid, 1024>>>(h, Wmu, Wlv, g, N);
    agg_kernel<false, true><<<agg_grid, 256>>>(g, bmu, blv, out, N);
}

// round 3
// speedup vs baseline: 1.8760x; 1.4655x over previous
#include <cuda_runtime.h>
#include <cuda_bf16.h>

// GCN encoder: 2x GCNConv(relu) + fused mu/logvar GCNConv heads.
//   deg/dis -> CSR build (histogram + multi-block scan + cursor fill) ->
//   per layer: [tiled GEMM (f32x2): g = (X@W) * dis] -> [AGG pull, warp/node, 4x unrolled]
// No fp32 atomics anywhere; CSR rebuilt every launch (deterministic work).

#define NMAX 100000
#define EMAX 1600000
#define SCAN_B 1024

__device__ __align__(16) float g_buf[(size_t)NMAX * 64];
__device__ __align__(16) float h_buf[(size_t)NMAX * 64];
__device__ float dis_buf[NMAX];
__device__ int   deg_buf[NMAX];
__device__ int   offs_buf[NMAX + 1];
__device__ int   cursor_buf[NMAX];
__device__ int   csr_buf[EMAX];
__device__ int   block_sums[128];

// ---------------------------------------------------------------------------
__global__ void zero_deg_kernel(int N) {
    int i = blockIdx.x * blockDim.x + threadIdx.x;
    if (i < N) deg_buf[i] = 0;
}

__global__ void count_deg_kernel(const int* __restrict__ ei, int E) {
    int e = blockIdx.x * blockDim.x + threadIdx.x;
    if (e < E) atomicAdd(&deg_buf[ei[E + e]], 1);
}

// Phase 1: per-block reduction of 1024 elements.
__global__ void reduce_deg_kernel(int N) {
    int idx = blockIdx.x * SCAN_B + threadIdx.x;
    int v = (idx < N) ? deg_buf[idx] : 0;
    #pragma unroll
    for (int o = 16; o; o >>= 1) v += __shfl_down_sync(0xffffffffu, v, o);
    __shared__ int ws[32];
    int lane = threadIdx.x & 31, w = threadIdx.x >> 5;
    if (lane == 0) ws[w] = v;
    __syncthreads();
    if (w == 0) {
        int s = ws[lane];
        #pragma unroll
        for (int o = 16; o; o >>= 1) s += __shfl_down_sync(0xffffffffu, s, o);
        if (lane == 0) block_sums[blockIdx.x] = s;
    }
}

// Phase 2: scan the (<=128) block sums.
__global__ void scan_sums_kernel(int nb, int N) {
    int tid = threadIdx.x;
    __shared__ int sh[128];
    int v = (tid < nb) ? block_sums[tid] : 0;
    sh[tid] = v;
    __syncthreads();
    #pragma unroll
    for (int o = 1; o < 128; o <<= 1) {
        int t = (tid >= o) ? sh[tid - o] : 0;
        __syncthreads();
        sh[tid] += t;
        __syncthreads();
    }
    if (tid < nb) block_sums[tid] = sh[tid] - v;   // exclusive
    if (tid == 0) offs_buf[N] = sh[127];
}

// Phase 3: per-block scan + block offset; fuse dis = rsqrt(deg+1).
__global__ void scan_deg_kernel(int N) {
    int idx = blockIdx.x * SCAN_B + threadIdx.x;
    int v = (idx < N) ? deg_buf[idx] : 0;
    int lane = threadIdx.x & 31, w = threadIdx.x >> 5;
    int s = v;
    #pragma unroll
    for (int o = 1; o < 32; o <<= 1) {
        int t = __shfl_up_sync(0xffffffffu, s, o);
        if (lane >= o) s += t;
    }
    __shared__ int ws[32];
    if (lane == 31) ws[w] = s;
    __syncthreads();
    if (w == 0) {
        int t = ws[lane];
        #pragma unroll
        for (int o = 1; o < 32; o <<= 1) {
            int u = __shfl_up_sync(0xffffffffu, t, o);
            if (lane >= o) t += u;
        }
        ws[lane] = t;
    }
    __syncthreads();
    int excl = s - v + (w > 0 ? ws[w - 1] : 0) + block_sums[blockIdx.x];
    if (idx < N) {
        offs_buf[idx]   = excl;
        cursor_buf[idx] = excl;
        dis_buf[idx]    = rsqrtf((float)v + 1.0f);
    }
}

__global__ void fill_csr_kernel(const int* __restrict__ ei, int E) {
    int e = blockIdx.x * blockDim.x + threadIdx.x;
    if (e < E) {
        int dst = ei[E + e];
        int p = atomicAdd(&cursor_buf[dst], 1);
        csr_buf[p] = ei[e];  // src
    }
}

// ---------------------------------------------------------------------------
// Tiled GEMM + row-scale: out[i, 0:64] = (X[i, 0:K] @ W) * dis[i]
// 64 rows x 64 cols per block, 128 threads, thread = 4 rows x 8 cols.
// Inner loop uses packed fma.rn.f32x2 (2 MACs/instr).
template <int K, bool COMBINED>
__global__ void __launch_bounds__(128, 3)
gemm_tile_kernel(const float* __restrict__ X,
                 const float* __restrict__ Wa,
                 const float* __restrict__ Wb,
                 float* __restrict__ out, int N)
{
    constexpr int KT = 64;
    constexpr int STAGES = K / KT;
    __shared__ float Xs[64][KT + 1];           // +1 pad: conflict-free x reads
    __shared__ __align__(16) float Ws[KT][64];

    int tid = threadIdx.x;
    int tx = tid & 7;     // 8 col-groups of 8 cols
    int ty = tid >> 3;    // 16 row-groups of 4 rows
    int row0 = blockIdx.x * 64;

    unsigned long long acc[4][4];
    #pragma unroll
    for (int r = 0; r < 4; r++)
        #pragma unroll
        for (int c = 0; c < 4; c++) acc[r][c] = 0ull;

    for (int kt = 0; kt < STAGES; kt++) {
        // stage W[kt*KT .. +KT][0:64]
        for (int i = tid; i < KT * 64; i += 128) {
            int k = i >> 6, j = i & 63;
            float v;
            if (COMBINED) v = (j < 32) ? Wa[(kt * KT + k) * 32 + j]
                                       : Wb[(kt * KT + k) * 32 + (j - 32)];
            else          v = Wa[(kt * KT + k) * 64 + j];
            Ws[k][j] = v;
        }
        // stage X rows [row0..row0+63][kt*KT .. +KT], coalesced float4 reads
        for (int i = tid; i < 64 * (KT / 4); i += 128) {
            int r  = i / (KT / 4);
            int c4 = i % (KT / 4);
            int gr = row0 + r; if (gr >= N) gr = N - 1;
            float4 v = *(const float4*)(X + (size_t)gr * K + kt * KT + c4 * 4);
            Xs[r][c4 * 4 + 0] = v.x; Xs[r][c4 * 4 + 1] = v.y;
            Xs[r][c4 * 4 + 2] = v.z; Xs[r][c4 * 4 + 3] = v.w;
        }
        __syncthreads();

        #pragma unroll 8
        for (int k = 0; k < KT; k++) {
            ulonglong2 wA = *(const ulonglong2*)&Ws[k][tx * 8];
            ulonglong2 wB = *(const ulonglong2*)&Ws[k][tx * 8 + 4];
            #pragma unroll
            for (int r = 0; r < 4; r++) {
                float xv = Xs[ty * 4 + r][k];
                unsigned long long xp;
                asm("mov.b64 %0, {%1, %1};" : "=l"(xp) : "f"(xv));
                asm("fma.rn.f32x2 %0, %1, %2, %0;" : "+l"(acc[r][0]) : "l"(xp), "l"(wA.x));
                asm("fma.rn.f32x2 %0, %1, %2, %0;" : "+l"(acc[r][1]) : "l"(xp), "l"(wA.y));
                asm("fma.rn.f32x2 %0, %1, %2, %0;" : "+l"(acc[r][2]) : "l"(xp), "l"(wB.x));
                asm("fma.rn.f32x2 %0, %1, %2, %0;" : "+l"(acc[r][3]) : "l"(xp), "l"(wB.y));
            }
        }
        __syncthreads();
    }

    // epilogue: scale by dis[row], store 8 cols as two float4
    #pragma unroll
    for (int r = 0; r < 4; r++) {
        int gr = row0 + ty * 4 + r;
        if (gr < N) {
            float d = dis_buf[gr];
            float o[8];
            #pragma unroll
            for (int c = 0; c < 4; c++) {
                float lo, hi;
                asm("mov.b64 {%0, %1}, %2;" : "=f"(lo), "=f"(hi) : "l"(acc[r][c]));
                o[2 * c]     = lo * d;
                o[2 * c + 1] = hi * d;
            }
            float4* dst = (float4*)(out + (size_t)gr * 64 + tx * 8);
            dst[0] = make_float4(o[0], o[1], o[2], o[3]);
            dst[1] = make_float4(o[4], o[5], o[6], o[7]);
        }
    }
}

// ---------------------------------------------------------------------------
// Pull aggregation: one warp per dst node, lane holds cols {2l, 2l+1} (float2).
// 4x unrolled gathers with independent accumulators for MLP.
template <bool RELU, bool SPLIT>
__global__ void agg_kernel(const float* __restrict__ g,
                           const float* __restrict__ ba,
                           const float* __restrict__ bb,
                           float* __restrict__ out, int N)
{
    int warp = (int)((blockIdx.x * (unsigned)blockDim.x + threadIdx.x) >> 5);
    int lane = threadIdx.x & 31;
    if (warp >= N) return;
    int row = warp;

    const float2* gp = (const float2*)g;
    float2 a0 = gp[(size_t)row * 32 + lane];   // self-loop term
    float2 a1 = make_float2(0.f, 0.f);
    float2 a2 = make_float2(0.f, 0.f);
    float2 a3 = make_float2(0.f, 0.f);

    int beg = offs_buf[row];
    int end = offs_buf[row + 1];
    int e = beg;
    for (; e + 3 < end; e += 4) {
        int s0 = csr_buf[e];
        int s1 = csr_buf[e + 1];
        int s2 = csr_buf[e + 2];
        int s3 = csr_buf[e + 3];
        float2 v0 = gp[(size_t)s0 * 32 + lane];
        float2 v1 = gp[(size_t)s1 * 32 + lane];
        float2 v2 = gp[(size_t)s2 * 32 + lane];
        float2 v3 = gp[(size_t)s3 * 32 + lane];
        a0.x += v0.x; a0.y += v0.y;
        a1.x += v1.x; a1.y += v1.y;
        a2.x += v2.x; a2.y += v2.y;
        a3.x += v3.x; a3.y += v3.y;
    }
    for (; e < end; e++) {
        int s = csr_buf[e];
        float2 v = gp[(size_t)s * 32 + lane];
        a0.x += v.x; a0.y += v.y;
    }
    a0.x += a1.x + a2.x + a3.x;
    a0.y += a1.y + a2.y + a3.y;

    float d = dis_buf[row];
    int c0 = 2 * lane;
    float bb0, bb1;
    if (SPLIT) {
        bb0 = (c0 < 32)     ? ba[c0]     : bb[c0 - 32];
        bb1 = (c0 + 1 < 32) ? ba[c0 + 1] : bb[c0 + 1 - 32];
    } else {
        bb0 = ba[c0];
        bb1 = ba[c0 + 1];
    }
    float r0 = fmaf(d, a0.x, bb0);
    float r1 = fmaf(d, a0.y, bb1);
    if (RELU) { r0 = fmaxf(r0, 0.f); r1 = fmaxf(r1, 0.f); }

    if (SPLIT) {
        if (lane < 16) {
            ((float2*)out)[(size_t)row * 16 + lane] = make_float2(r0, r1);               // mu
        } else {
            ((float2*)(out + (size_t)N * 32))[(size_t)row * 16 + (lane - 16)] = make_float2(r0, r1); // logvar
        }
    } else {
        ((float2*)out)[(size_t)row * 32 + lane] = make_float2(r0, r1);
    }
}

// ---------------------------------------------------------------------------
extern "C" void kernel_launch(void* const* d_in, const int* in_sizes, int n_in,
                              void* d_out, int out_size)
{
    const float* x   = (const float*)d_in[0];
    const int*   ei  = (const int*)  d_in[1];
    const float* W1  = (const float*)d_in[2];
    const float* b1  = (const float*)d_in[3];
    const float* W2  = (const float*)d_in[4];
    const float* b2  = (const float*)d_in[5];
    const float* Wmu = (const float*)d_in[6];
    const float* bmu = (const float*)d_in[7];
    const float* Wlv = (const float*)d_in[8];
    const float* blv = (const float*)d_in[9];
    float* out = (float*)d_out;

    int N = in_sizes[0] / 128;
    int E = in_sizes[1] / 2;
    int nb = (N + SCAN_B - 1) / SCAN_B;

    float* g = nullptr;
    float* h = nullptr;
    cudaGetSymbolAddress((void**)&g, g_buf);
    cudaGetSymbolAddress((void**)&h, h_buf);

    // ---- degree / normalization / CSR build ----
    zero_deg_kernel<<<(N + 255) / 256, 256>>>(N);
    count_deg_kernel<<<(E + 255) / 256, 256>>>(ei, E);
    reduce_deg_kernel<<<nb, SCAN_B>>>(N);
    scan_sums_kernel<<<1, 128>>>(nb, N);
    scan_deg_kernel<<<nb, SCAN_B>>>(N);
    fill_csr_kernel<<<(E + 255) / 256, 256>>>(ei, E);

    int gemm_grid = (N + 63) / 64;
    int agg_grid  = (N + 7) / 8;        // 256 threads = 8 warps = 8 nodes / block

    // ---- layer 1: x(128) -> h(64), relu ----
    gemm_tile_kernel<128, false><<<gemm_grid, 128>>>(x, W1, nullptr, g, N);
    agg_kernel<true, false><<<agg_grid, 256>>>(g, b1, nullptr, h, N);

    // ---- layer 2: h(64) -> h(64), relu ----
    gemm_tile_kernel<64, false><<<gemm_grid, 128>>>(h, W2, nullptr, g, N);
    agg_kernel<true, false><<<agg_grid, 256>>>(g, b2, nullptr, h, N);

    // ---- heads: h(64) -> [mu(32) | logvar(32)] ----
    gemm_tile_kernel<64, true><<<gemm_grid, 128>>>(h, Wmu, Wlv, g, N);
    agg_kernel<false, true><<<agg_grid, 256>>>(g, bmu, blv, out, N);
}

// round 4
// speedup vs baseline: 1.8884x; 1.0066x over previous
#include <cuda_runtime.h>
#include <cuda_bf16.h>

// GCN encoder: 2x GCNConv(relu) + fused mu/logvar GCNConv heads.
//   deg -> dis -> [gemm1 hoisted early for profiling] -> scan -> CSR fill ->
//   per layer: [tiled GEMM (f32x2): g = (X@W) * dis] -> [AGG pull: half-warp/edge float4, 8 edges in flight]
// No fp32 atomics anywhere; CSR rebuilt every launch (deterministic work).

#define NMAX 100000
#define EMAX 1600000
#define SCAN_B 1024

__device__ __align__(16) float g_buf[(size_t)NMAX * 64];
__device__ __align__(16) float h_buf[(size_t)NMAX * 64];
__device__ float dis_buf[NMAX];
__device__ int   deg_buf[NMAX];
__device__ int   offs_buf[NMAX + 1];
__device__ int   cursor_buf[NMAX];
__device__ int   csr_buf[EMAX];
__device__ int   block_sums[128];

// ---------------------------------------------------------------------------
__global__ void zero_deg_kernel(int N) {
    int i = blockIdx.x * blockDim.x + threadIdx.x;
    if (i < N) deg_buf[i] = 0;
}

__global__ void count_deg_kernel(const int* __restrict__ ei, int E) {
    int e = blockIdx.x * blockDim.x + threadIdx.x;
    if (e < E) atomicAdd(&deg_buf[ei[E + e]], 1);
}

__global__ void dis_kernel(int N) {
    int i = blockIdx.x * blockDim.x + threadIdx.x;
    if (i < N) dis_buf[i] = rsqrtf((float)deg_buf[i] + 1.0f);
}

// Phase 1: per-block reduction of 1024 elements.
__global__ void reduce_deg_kernel(int N) {
    int idx = blockIdx.x * SCAN_B + threadIdx.x;
    int v = (idx < N) ? deg_buf[idx] : 0;
    #pragma unroll
    for (int o = 16; o; o >>= 1) v += __shfl_down_sync(0xffffffffu, v, o);
    __shared__ int ws[32];
    int lane = threadIdx.x & 31, w = threadIdx.x >> 5;
    if (lane == 0) ws[w] = v;
    __syncthreads();
    if (w == 0) {
        int s = ws[lane];
        #pragma unroll
        for (int o = 16; o; o >>= 1) s += __shfl_down_sync(0xffffffffu, s, o);
        if (lane == 0) block_sums[blockIdx.x] = s;
    }
}

// Phase 2: scan the (<=128) block sums.
__global__ void scan_sums_kernel(int nb, int N) {
    int tid = threadIdx.x;
    __shared__ int sh[128];
    int v = (tid < nb) ? block_sums[tid] : 0;
    sh[tid] = v;
    __syncthreads();
    #pragma unroll
    for (int o = 1; o < 128; o <<= 1) {
        int t = (tid >= o) ? sh[tid - o] : 0;
        __syncthreads();
        sh[tid] += t;
        __syncthreads();
    }
    if (tid < nb) block_sums[tid] = sh[tid] - v;   // exclusive
    if (tid == 0) offs_buf[N] = sh[127];
}

// Phase 3: per-block scan + block offset -> offs/cursor.
__global__ void scan_deg_kernel(int N) {
    int idx = blockIdx.x * SCAN_B + threadIdx.x;
    int v = (idx < N) ? deg_buf[idx] : 0;
    int lane = threadIdx.x & 31, w = threadIdx.x >> 5;
    int s = v;
    #pragma unroll
    for (int o = 1; o < 32; o <<= 1) {
        int t = __shfl_up_sync(0xffffffffu, s, o);
        if (lane >= o) s += t;
    }
    __shared__ int ws[32];
    if (lane == 31) ws[w] = s;
    __syncthreads();
    if (w == 0) {
        int t = ws[lane];
        #pragma unroll
        for (int o = 1; o < 32; o <<= 1) {
            int u = __shfl_up_sync(0xffffffffu, t, o);
            if (lane >= o) t += u;
        }
        ws[lane] = t;
    }
    __syncthreads();
    int excl = s - v + (w > 0 ? ws[w - 1] : 0) + block_sums[blockIdx.x];
    if (idx < N) {
        offs_buf[idx]   = excl;
        cursor_buf[idx] = excl;
    }
}

__global__ void fill_csr_kernel(const int* __restrict__ ei, int E) {
    int e = blockIdx.x * blockDim.x + threadIdx.x;
    if (e < E) {
        int dst = ei[E + e];
        int p = atomicAdd(&cursor_buf[dst], 1);
        csr_buf[p] = ei[e];  // src
    }
}

// ---------------------------------------------------------------------------
// Tiled GEMM + row-scale: out[i, 0:64] = (X[i, 0:K] @ W) * dis[i]
// 64 rows x 64 cols per block, 128 threads, thread = 4 rows x 8 cols.
// Inner loop uses packed fma.rn.f32x2 (2 MACs/instr).
template <int K, bool COMBINED>
__global__ void __launch_bounds__(128, 3)
gemm_tile_kernel(const float* __restrict__ X,
                 const float* __restrict__ Wa,
                 const float* __restrict__ Wb,
                 float* __restrict__ out, int N)
{
    constexpr int KT = 64;
    constexpr int STAGES = K / KT;
    __shared__ float Xs[64][KT + 1];           // +1 pad: conflict-free x reads
    __shared__ __align__(16) float Ws[KT][64];

    int tid = threadIdx.x;
    int tx = tid & 7;     // 8 col-groups of 8 cols
    int ty = tid >> 3;    // 16 row-groups of 4 rows
    int row0 = blockIdx.x * 64;

    unsigned long long acc[4][4];
    #pragma unroll
    for (int r = 0; r < 4; r++)
        #pragma unroll
        for (int c = 0; c < 4; c++) acc[r][c] = 0ull;

    for (int kt = 0; kt < STAGES; kt++) {
        for (int i = tid; i < KT * 64; i += 128) {
            int k = i >> 6, j = i & 63;
            float v;
            if (COMBINED) v = (j < 32) ? Wa[(kt * KT + k) * 32 + j]
                                       : Wb[(kt * KT + k) * 32 + (j - 32)];
            else          v = Wa[(kt * KT + k) * 64 + j];
            Ws[k][j] = v;
        }
        for (int i = tid; i < 64 * (KT / 4); i += 128) {
            int r  = i / (KT / 4);
            int c4 = i % (KT / 4);
            int gr = row0 + r; if (gr >= N) gr = N - 1;
            float4 v = *(const float4*)(X + (size_t)gr * K + kt * KT + c4 * 4);
            Xs[r][c4 * 4 + 0] = v.x; Xs[r][c4 * 4 + 1] = v.y;
            Xs[r][c4 * 4 + 2] = v.z; Xs[r][c4 * 4 + 3] = v.w;
        }
        __syncthreads();

        #pragma unroll 8
        for (int k = 0; k < KT; k++) {
            ulonglong2 wA = *(const ulonglong2*)&Ws[k][tx * 8];
            ulonglong2 wB = *(const ulonglong2*)&Ws[k][tx * 8 + 4];
            #pragma unroll
            for (int r = 0; r < 4; r++) {
                float xv = Xs[ty * 4 + r][k];
                unsigned long long xp;
                asm("mov.b64 %0, {%1, %1};" : "=l"(xp) : "f"(xv));
                asm("fma.rn.f32x2 %0, %1, %2, %0;" : "+l"(acc[r][0]) : "l"(xp), "l"(wA.x));
                asm("fma.rn.f32x2 %0, %1, %2, %0;" : "+l"(acc[r][1]) : "l"(xp), "l"(wA.y));
                asm("fma.rn.f32x2 %0, %1, %2, %0;" : "+l"(acc[r][2]) : "l"(xp), "l"(wB.x));
                asm("fma.rn.f32x2 %0, %1, %2, %0;" : "+l"(acc[r][3]) : "l"(xp), "l"(wB.y));
            }
        }
        __syncthreads();
    }

    #pragma unroll
    for (int r = 0; r < 4; r++) {
        int gr = row0 + ty * 4 + r;
        if (gr < N) {
            float d = dis_buf[gr];
            float o[8];
            #pragma unroll
            for (int c = 0; c < 4; c++) {
                float lo, hi;
                asm("mov.b64 {%0, %1}, %2;" : "=f"(lo), "=f"(hi) : "l"(acc[r][c]));
                o[2 * c]     = lo * d;
                o[2 * c + 1] = hi * d;
            }
            float4* dst = (float4*)(out + (size_t)gr * 64 + tx * 8);
            dst[0] = make_float4(o[0], o[1], o[2], o[3]);
            dst[1] = make_float4(o[4], o[5], o[6], o[7]);
        }
    }
}

// ---------------------------------------------------------------------------
// Pull aggregation: one warp per dst node. Half-warp (16 lanes x float4)
// covers one edge's 64-float row; warp processes 2 edges per slot, 4 slots
// unrolled => 8 edges (16 cache lines) in flight per warp iteration.
template <bool RELU, bool SPLIT>
__global__ void agg_kernel(const float* __restrict__ g,
                           const float* __restrict__ ba,
                           const float* __restrict__ bb,
                           float* __restrict__ out, int N)
{
    int warp = (int)((blockIdx.x * (unsigned)blockDim.x + threadIdx.x) >> 5);
    int lane = threadIdx.x & 31;
    if (warp >= N) return;
    int row  = warp;
    int half = lane >> 4;      // 0 or 1
    int li   = lane & 15;      // position within half: cols 4*li..4*li+3

    const float4* gp = (const float4*)g;   // 16 float4 per row

    float4 a0 = make_float4(0.f, 0.f, 0.f, 0.f);
    float4 a1 = a0, a2 = a0, a3 = a0;
    if (half == 0) a0 = gp[(size_t)row * 16 + li];   // self-loop term

    int beg = offs_buf[row];
    int end = offs_buf[row + 1];
    int e = beg;
    for (; e + 7 < end; e += 8) {
        int s0 = csr_buf[e     + half];
        int s1 = csr_buf[e + 2 + half];
        int s2 = csr_buf[e + 4 + half];
        int s3 = csr_buf[e + 6 + half];
        float4 v0 = gp[(size_t)s0 * 16 + li];
        float4 v1 = gp[(size_t)s1 * 16 + li];
        float4 v2 = gp[(size_t)s2 * 16 + li];
        float4 v3 = gp[(size_t)s3 * 16 + li];
        a0.x += v0.x; a0.y += v0.y; a0.z += v0.z; a0.w += v0.w;
        a1.x += v1.x; a1.y += v1.y; a1.z += v1.z; a1.w += v1.w;
        a2.x += v2.x; a2.y += v2.y; a2.z += v2.z; a2.w += v2.w;
        a3.x += v3.x; a3.y += v3.y; a3.z += v3.z; a3.w += v3.w;
    }
    for (; e + 1 < end; e += 2) {
        int s = csr_buf[e + half];
        float4 v = gp[(size_t)s * 16 + li];
        a0.x += v.x; a0.y += v.y; a0.z += v.z; a0.w += v.w;
    }
    if (e < end && half == 0) {
        float4 v = gp[(size_t)csr_buf[e] * 16 + li];
        a0.x += v.x; a0.y += v.y; a0.z += v.z; a0.w += v.w;
    }
    a0.x += a1.x + a2.x + a3.x;
    a0.y += a1.y + a2.y + a3.y;
    a0.z += a1.z + a2.z + a3.z;
    a0.w += a1.w + a2.w + a3.w;

    // combine halves (lanes l and l^16 hold same columns)
    a0.x += __shfl_xor_sync(0xffffffffu, a0.x, 16);
    a0.y += __shfl_xor_sync(0xffffffffu, a0.y, 16);
    a0.z += __shfl_xor_sync(0xffffffffu, a0.z, 16);
    a0.w += __shfl_xor_sync(0xffffffffu, a0.w, 16);

    if (half == 0) {
        float d = dis_buf[row];
        int c0 = 4 * li;
        float4 b4;
        if (SPLIT) {
            b4.x = (c0     < 32) ? ba[c0]     : bb[c0 - 32];
            b4.y = (c0 + 1 < 32) ? ba[c0 + 1] : bb[c0 + 1 - 32];
            b4.z = (c0 + 2 < 32) ? ba[c0 + 2] : bb[c0 + 2 - 32];
            b4.w = (c0 + 3 < 32) ? ba[c0 + 3] : bb[c0 + 3 - 32];
        } else {
            b4 = *(const float4*)(ba + c0);
        }
        float4 r;
        r.x = fmaf(d, a0.x, b4.x);
        r.y = fmaf(d, a0.y, b4.y);
        r.z = fmaf(d, a0.z, b4.z);
        r.w = fmaf(d, a0.w, b4.w);
        if (RELU) {
            r.x = fmaxf(r.x, 0.f); r.y = fmaxf(r.y, 0.f);
            r.z = fmaxf(r.z, 0.f); r.w = fmaxf(r.w, 0.f);
        }
        if (SPLIT) {
            if (li < 8) ((float4*)out)[(size_t)row * 8 + li] = r;                          // mu
            else        ((float4*)(out + (size_t)N * 32))[(size_t)row * 8 + (li - 8)] = r; // logvar
        } else {
            ((float4*)out)[(size_t)row * 16 + li] = r;
        }
    }
}

// ---------------------------------------------------------------------------
extern "C" void kernel_launch(void* const* d_in, const int* in_sizes, int n_in,
                              void* d_out, int out_size)
{
    const float* x   = (const float*)d_in[0];
    const int*   ei  = (const int*)  d_in[1];
    const float* W1  = (const float*)d_in[2];
    const float* b1  = (const float*)d_in[3];
    const float* W2  = (const float*)d_in[4];
    const float* b2  = (const float*)d_in[5];
    const float* Wmu = (const float*)d_in[6];
    const float* bmu = (const float*)d_in[7];
    const float* Wlv = (const float*)d_in[8];
    const float* blv = (const float*)d_in[9];
    float* out = (float*)d_out;

    int N = in_sizes[0] / 128;
    int E = in_sizes[1] / 2;
    int nb = (N + SCAN_B - 1) / SCAN_B;

    float* g = nullptr;
    float* h = nullptr;
    cudaGetSymbolAddress((void**)&g, g_buf);
    cudaGetSymbolAddress((void**)&h, h_buf);

    int gemm_grid = (N + 63) / 64;
    int agg_grid  = (N + 7) / 8;        // 256 threads = 8 warps = 8 nodes / block

    // ---- degree / dis, gemm1 hoisted (only needs dis), then CSR build ----
    zero_deg_kernel<<<(N + 255) / 256, 256>>>(N);                       // idx 0
    count_deg_kernel<<<(E + 255) / 256, 256>>>(ei, E);                  // idx 1
    dis_kernel<<<(N + 255) / 256, 256>>>(N);                            // idx 2
    gemm_tile_kernel<128, false><<<gemm_grid, 128>>>(x, W1, nullptr, g, N); // idx 3 (profiled)
    reduce_deg_kernel<<<nb, SCAN_B>>>(N);
    scan_sums_kernel<<<1, 128>>>(nb, N);
    scan_deg_kernel<<<nb, SCAN_B>>>(N);
    fill_csr_kernel<<<(E + 255) / 256, 256>>>(ei, E);

    // ---- layer 1 agg ----
    agg_kernel<true, false><<<agg_grid, 256>>>(g, b1, nullptr, h, N);

    // ---- layer 2: h(64) -> h(64), relu ----
    gemm_tile_kernel<64, false><<<gemm_grid, 128>>>(h, W2, nullptr, g, N);
    agg_kernel<true, false><<<agg_grid, 256>>>(g, b2, nullptr, h, N);

    // ---- heads: h(64) -> [mu(32) | logvar(32)] ----
    gemm_tile_kernel<64, true><<<gemm_grid, 128>>>(h, Wmu, Wlv, g, N);
    agg_kernel<false, true><<<agg_grid, 256>>>(g, bmu, blv, out, N);
}